// round 1
// baseline (speedup 1.0000x reference)
#include <cuda_runtime.h>

// DPLSafePolicy: out[b,a] = softmax-normalized base*(1-unsafe) where
// ghost/pacman/base are softmaxes of x@W+b. Fused skinny GEMM (N=13) + epilogue.
//
// Strategy: weights packed+swizzled in SMEM ([c][16] floats, 128KB, conflict-free
// broadcast LDS.128), x streamed once (HBM-bound, 134MB), fma.rn.f32x2 packed
// accumulation (7 packed accumulators = 13 outputs + 1 pad), warp = 4 rows x
// 8 column-groups, 3-level shfl reduce, epilogue on 4 lanes.

#define GRIDX 148
#define NTHR 256
#define NWARPS (GRIDX * (NTHR / 32))
#define HDIM 2048
#define NROWS 16384
#define RPC 4
#define NCHUNK (NROWS / RPC)
// smem floats: max addr = 2047*16 + 7*4 + 15 + 1 = 32796 -> pad a bit
#define SMEM_FLOATS (HDIM * 16 + 64)
#define SMEM_BYTES (SMEM_FLOATS * 4)

typedef unsigned long long u64;

__device__ __forceinline__ u64 splat2(float x) {
    u64 r; asm("mov.b64 %0, {%1, %1};" : "=l"(r) : "f"(x)); return r;
}
__device__ __forceinline__ u64 fma2(u64 a, u64 b, u64 c) {
    u64 d; asm("fma.rn.f32x2 %0, %1, %2, %3;" : "=l"(d) : "l"(a), "l"(b), "l"(c)); return d;
}
__device__ __forceinline__ void unpack2(u64 a, float& lo, float& hi) {
    asm("mov.b64 {%0, %1}, %2;" : "=f"(lo), "=f"(hi) : "l"(a));
}

__global__ void __launch_bounds__(NTHR, 1) policy_kernel(
    const float* __restrict__ x,
    const float* __restrict__ Wg, const float* __restrict__ bg,
    const float* __restrict__ Wp, const float* __restrict__ bp,
    const float* __restrict__ Wa, const float* __restrict__ ba,
    float* __restrict__ out)
{
    extern __shared__ float sw[];
    const int tid = threadIdx.x;

    // Pack weights into smem: sw[c*16 + (c>>8)*4 + j], j=0..3 Wg, 4..7 Wp, 8..12 Wa, 13..15 zero
    for (int idx = tid; idx < HDIM * 16; idx += NTHR) {
        int c = idx >> 4, j = idx & 15;
        float v = 0.0f;
        if (j < 4)       v = Wg[c * 4 + j];
        else if (j < 8)  v = Wp[c * 4 + (j - 4)];
        else if (j < 13) v = Wa[c * 5 + (j - 8)];
        sw[(c << 4) + ((c >> 8) << 2) + j] = v;
    }
    __syncthreads();

    const int warp = tid >> 5, lane = tid & 31;
    const int rsub = lane & 3;       // row within chunk (0..3)
    const int g = lane >> 2;         // column group (0..7), 256 cols each
    const float* wbase = sw + g * 4100;   // (g*256)*16 + g*4

    for (int chunk = warp * GRIDX + blockIdx.x; chunk < NCHUNK; chunk += NWARPS) {
        const int r0 = chunk * RPC;
        const float* xb = x + (size_t)(r0 + rsub) * HDIM + (g << 8);

        u64 acc0 = 0, acc1 = 0, acc2 = 0, acc3 = 0, acc4 = 0, acc5 = 0, acc6 = 0;

        float4 a0 = *(const float4*)(xb);
        float4 a1 = *(const float4*)(xb + 4);

#define COLSTEP(xv, off) { \
            const double2* q = (const double2*)(wbase + (off)); \
            double2 q0 = q[0], q1 = q[1], q2 = q[2], q3 = q[3]; \
            u64 xx = splat2(xv); \
            acc0 = fma2(xx, __double_as_longlong(q0.x), acc0); \
            acc1 = fma2(xx, __double_as_longlong(q0.y), acc1); \
            acc2 = fma2(xx, __double_as_longlong(q1.x), acc2); \
            acc3 = fma2(xx, __double_as_longlong(q1.y), acc3); \
            acc4 = fma2(xx, __double_as_longlong(q2.x), acc4); \
            acc5 = fma2(xx, __double_as_longlong(q2.y), acc5); \
            acc6 = fma2(xx, __double_as_longlong(q3.x), acc6); \
        }
#define GRP8(cl, b0, b1) { \
            int wo = (cl) << 4; \
            COLSTEP(b0.x, wo);       COLSTEP(b0.y, wo + 16); \
            COLSTEP(b0.z, wo + 32);  COLSTEP(b0.w, wo + 48); \
            COLSTEP(b1.x, wo + 64);  COLSTEP(b1.y, wo + 80); \
            COLSTEP(b1.z, wo + 96);  COLSTEP(b1.w, wo + 112); \
        }

#pragma unroll 1
        for (int cl = 0; cl < 248; cl += 8) {
            float4 n0 = *(const float4*)(xb + cl + 8);
            float4 n1 = *(const float4*)(xb + cl + 12);
            GRP8(cl, a0, a1);
            a0 = n0; a1 = n1;
        }
        GRP8(248, a0, a1);

        // Unpack 7 packed accumulators -> 13 logit partials (+1 pad, weight==0 so exact 0)
        float v[13]; float pad;
        unpack2(acc0, v[0], v[1]);   unpack2(acc1, v[2], v[3]);
        unpack2(acc2, v[4], v[5]);   unpack2(acc3, v[6], v[7]);
        unpack2(acc4, v[8], v[9]);   unpack2(acc5, v[10], v[11]);
        unpack2(acc6, v[12], pad);

        // Reduce across the 8 column groups (lane bits 2,3,4)
#pragma unroll
        for (int off = 4; off <= 16; off <<= 1) {
#pragma unroll
            for (int j = 0; j < 13; j++)
                v[j] += __shfl_xor_sync(0xffffffffu, v[j], off);
        }

        if (g == 0) {
            const int row = r0 + rsub;
            // ghost softmax
            float l0 = v[0] + bg[0], l1 = v[1] + bg[1], l2 = v[2] + bg[2], l3 = v[3] + bg[3];
            float mg = fmaxf(fmaxf(l0, l1), fmaxf(l2, l3));
            float eg0 = __expf(l0 - mg), eg1 = __expf(l1 - mg), eg2 = __expf(l2 - mg), eg3 = __expf(l3 - mg);
            float sg = eg0 + eg1 + eg2 + eg3;
            // pacman softmax
            float p0 = v[4] + bp[0], p1 = v[5] + bp[1], p2 = v[6] + bp[2], p3 = v[7] + bp[3];
            float mp = fmaxf(fmaxf(p0, p1), fmaxf(p2, p3));
            float ep0 = __expf(p0 - mp), ep1 = __expf(p1 - mp), ep2 = __expf(p2 - mp), ep3 = __expf(p3 - mp);
            float sp = ep0 + ep1 + ep2 + ep3;
            // action (base) softmax numerators (denominator cancels in final norm)
            float q0 = v[8] + ba[0], q1 = v[9] + ba[1], q2 = v[10] + ba[2], q3 = v[11] + ba[3], q4 = v[12] + ba[4];
            float ma = fmaxf(fmaxf(fmaxf(q0, q1), fmaxf(q2, q3)), q4);
            float ea0 = __expf(q0 - ma), ea1 = __expf(q1 - ma), ea2 = __expf(q2 - ma),
                  ea3 = __expf(q3 - ma), ea4 = __expf(q4 - ma);
            // unsafe probabilities (cells: 0=(0,0),1=(0,1),2=(1,0),3=(1,1))
            float t0 = ep0 * eg0 + ep1 * eg1 + ep2 * eg2 + ep3 * eg3;  // stay
            float t1 = ep0 * eg1 + ep2 * eg3;                           // up
            float t2 = ep1 * eg0 + ep3 * eg2;                           // down
            float inv = 1.0f / (sg * sp);
            float j0 = ea0 * (1.0f - t0 * inv);
            float j1 = ea1 * (1.0f - t1 * inv);
            float j2 = ea2 * (1.0f - t2 * inv);
            float s = j0 + j1 + j2 + ea3 + ea4;
            float is = 1.0f / s;
            float* o = out + (size_t)row * 5;
            o[0] = j0 * is; o[1] = j1 * is; o[2] = j2 * is; o[3] = ea3 * is; o[4] = ea4 * is;
        }
    }
}

extern "C" void kernel_launch(void* const* d_in, const int* in_sizes, int n_in,
                              void* d_out, int out_size)
{
    const float* x  = (const float*)d_in[0];
    const float* Wg = (const float*)d_in[1];
    const float* bg = (const float*)d_in[2];
    const float* Wp = (const float*)d_in[3];
    const float* bp = (const float*)d_in[4];
    const float* Wa = (const float*)d_in[5];
    const float* ba = (const float*)d_in[6];
    float* out = (float*)d_out;

    cudaFuncSetAttribute(policy_kernel, cudaFuncAttributeMaxDynamicSharedMemorySize, SMEM_BYTES);
    policy_kernel<<<GRIDX, NTHR, SMEM_BYTES>>>(x, Wg, bg, Wp, bp, Wa, ba, out);
}

// round 3
// speedup vs baseline: 1.2065x; 1.2065x over previous
#include <cuda_runtime.h>

// DPLSafePolicy fused skinny GEMM (16384x2048 @ 2048x13) + softmax/ProbLog epilogue.
// R2: raise occupancy (512 thr, reg cap 128 -> 16 warps/SM) + 16-col deep x prefetch
// to get ~32KB/SM of in-flight DRAM loads. Weights stay in 128KB padded smem,
// broadcast LDS.128, fma.rn.f32x2 packed accumulation.

#define GRIDX 148
#define NTHR 512
#define NWARPS (GRIDX * (NTHR / 32))
#define HDIM 2048
#define NROWS 16384
#define RPC 4
#define NCHUNK (NROWS / RPC)
#define SMEM_FLOATS (HDIM * 16 + 64)
#define SMEM_BYTES (SMEM_FLOATS * 4)

typedef unsigned long long u64;

__device__ __forceinline__ u64 splat2(float x) {
    u64 r; asm("mov.b64 %0, {%1, %1};" : "=l"(r) : "f"(x)); return r;
}
__device__ __forceinline__ u64 fma2(u64 a, u64 b, u64 c) {
    u64 d; asm("fma.rn.f32x2 %0, %1, %2, %3;" : "=l"(d) : "l"(a), "l"(b), "l"(c)); return d;
}
__device__ __forceinline__ void unpack2(u64 a, float& lo, float& hi) {
    asm("mov.b64 {%0, %1}, %2;" : "=f"(lo), "=f"(hi) : "l"(a));
}

__global__ void __launch_bounds__(NTHR, 1) policy_kernel(
    const float* __restrict__ x,
    const float* __restrict__ Wg, const float* __restrict__ bg,
    const float* __restrict__ Wp, const float* __restrict__ bp,
    const float* __restrict__ Wa, const float* __restrict__ ba,
    float* __restrict__ out)
{
    extern __shared__ float sw[];
    const int tid = threadIdx.x;

    // Pack weights: sw[c*16 + (c>>8)*4 + j], j=0..3 Wg, 4..7 Wp, 8..12 Wa, 13..15 zero
    for (int idx = tid; idx < HDIM * 16; idx += NTHR) {
        int c = idx >> 4, j = idx & 15;
        float v = 0.0f;
        if (j < 4)       v = Wg[c * 4 + j];
        else if (j < 8)  v = Wp[c * 4 + (j - 4)];
        else if (j < 13) v = Wa[c * 5 + (j - 8)];
        sw[(c << 4) + ((c >> 8) << 2) + j] = v;
    }
    __syncthreads();

    const int warp = tid >> 5, lane = tid & 31;
    const int rsub = lane & 3;       // row within chunk (0..3)
    const int g = lane >> 2;         // column group (0..7), 256 cols each
    const float* wbase = sw + g * 4100;   // (g*256)*16 + g*4

    for (int chunk = warp * GRIDX + blockIdx.x; chunk < NCHUNK; chunk += NWARPS) {
        const int r0 = chunk * RPC;
        const float* xb = x + (size_t)(r0 + rsub) * HDIM + (g << 8);

        u64 acc0 = 0, acc1 = 0, acc2 = 0, acc3 = 0, acc4 = 0, acc5 = 0, acc6 = 0;

        // stage buffers: 16 columns
        float4 c0 = *(const float4*)(xb);
        float4 c1 = *(const float4*)(xb + 4);
        float4 c2 = *(const float4*)(xb + 8);
        float4 c3 = *(const float4*)(xb + 12);

#define COLSTEP(xv, off) { \
            const double2* q = (const double2*)(wbase + (off)); \
            double2 q0 = q[0], q1 = q[1], q2 = q[2], q3 = q[3]; \
            u64 xx = splat2(xv); \
            acc0 = fma2(xx, __double_as_longlong(q0.x), acc0); \
            acc1 = fma2(xx, __double_as_longlong(q0.y), acc1); \
            acc2 = fma2(xx, __double_as_longlong(q1.x), acc2); \
            acc3 = fma2(xx, __double_as_longlong(q1.y), acc3); \
            acc4 = fma2(xx, __double_as_longlong(q2.x), acc4); \
            acc5 = fma2(xx, __double_as_longlong(q2.y), acc5); \
            acc6 = fma2(xx, __double_as_longlong(q3.x), acc6); \
        }
#define QUAD(cl, b) { \
            int wo = (cl) << 4; \
            COLSTEP(b.x, wo);      COLSTEP(b.y, wo + 16); \
            COLSTEP(b.z, wo + 32); COLSTEP(b.w, wo + 48); \
        }
#define GRP16(cl) { \
            QUAD((cl), c0); QUAD((cl) + 4, c1); \
            QUAD((cl) + 8, c2); QUAD((cl) + 12, c3); \
        }

#pragma unroll 1
        for (int cl = 0; cl < 240; cl += 16) {
            // prefetch next 16 columns before touching current stage
            float4 n0 = *(const float4*)(xb + cl + 16);
            float4 n1 = *(const float4*)(xb + cl + 20);
            float4 n2 = *(const float4*)(xb + cl + 24);
            float4 n3 = *(const float4*)(xb + cl + 28);
            GRP16(cl);
            c0 = n0; c1 = n1; c2 = n2; c3 = n3;
        }
        GRP16(240);

        // Unpack 7 packed accumulators -> 13 logit partials (+1 pad: weight==0)
        float v[13]; float pad;
        unpack2(acc0, v[0], v[1]);   unpack2(acc1, v[2], v[3]);
        unpack2(acc2, v[4], v[5]);   unpack2(acc3, v[6], v[7]);
        unpack2(acc4, v[8], v[9]);   unpack2(acc5, v[10], v[11]);
        unpack2(acc6, v[12], pad);

        // Reduce across the 8 column groups (lane bits 2,3,4)
#pragma unroll
        for (int off = 4; off <= 16; off <<= 1) {
#pragma unroll
            for (int j = 0; j < 13; j++)
                v[j] += __shfl_xor_sync(0xffffffffu, v[j], off);
        }

        if (g == 0) {
            const int row = r0 + rsub;
            // ghost softmax
            float l0 = v[0] + bg[0], l1 = v[1] + bg[1], l2 = v[2] + bg[2], l3 = v[3] + bg[3];
            float mg = fmaxf(fmaxf(l0, l1), fmaxf(l2, l3));
            float eg0 = __expf(l0 - mg), eg1 = __expf(l1 - mg), eg2 = __expf(l2 - mg), eg3 = __expf(l3 - mg);
            float sg = eg0 + eg1 + eg2 + eg3;
            // pacman softmax
            float p0 = v[4] + bp[0], p1 = v[5] + bp[1], p2 = v[6] + bp[2], p3 = v[7] + bp[3];
            float mp = fmaxf(fmaxf(p0, p1), fmaxf(p2, p3));
            float ep0 = __expf(p0 - mp), ep1 = __expf(p1 - mp), ep2 = __expf(p2 - mp), ep3 = __expf(p3 - mp);
            float sp = ep0 + ep1 + ep2 + ep3;
            // action softmax numerators
            float q0 = v[8] + ba[0], q1 = v[9] + ba[1], q2 = v[10] + ba[2], q3 = v[11] + ba[3], q4 = v[12] + ba[4];
            float ma = fmaxf(fmaxf(fmaxf(q0, q1), fmaxf(q2, q3)), q4);
            float ea0 = __expf(q0 - ma), ea1 = __expf(q1 - ma), ea2 = __expf(q2 - ma),
                  ea3 = __expf(q3 - ma), ea4 = __expf(q4 - ma);
            // unsafe terms (cells: 0=(0,0),1=(0,1),2=(1,0),3=(1,1))
            float t0 = ep0 * eg0 + ep1 * eg1 + ep2 * eg2 + ep3 * eg3;  // stay
            float t1 = ep0 * eg1 + ep2 * eg3;                           // up
            float t2 = ep1 * eg0 + ep3 * eg2;                           // down
            float inv = 1.0f / (sg * sp);
            float j0 = ea0 * (1.0f - t0 * inv);
            float j1 = ea1 * (1.0f - t1 * inv);
            float j2 = ea2 * (1.0f - t2 * inv);
            float s = j0 + j1 + j2 + ea3 + ea4;
            float is = 1.0f / s;
            float* o = out + (size_t)row * 5;
            o[0] = j0 * is; o[1] = j1 * is; o[2] = j2 * is; o[3] = ea3 * is; o[4] = ea4 * is;
        }
    }
}

extern "C" void kernel_launch(void* const* d_in, const int* in_sizes, int n_in,
                              void* d_out, int out_size)
{
    const float* x  = (const float*)d_in[0];
    const float* Wg = (const float*)d_in[1];
    const float* bg = (const float*)d_in[2];
    const float* Wp = (const float*)d_in[3];
    const float* bp = (const float*)d_in[4];
    const float* Wa = (const float*)d_in[5];
    const float* ba = (const float*)d_in[6];
    float* out = (float*)d_out;

    cudaFuncSetAttribute(policy_kernel, cudaFuncAttributeMaxDynamicSharedMemorySize, SMEM_BYTES);
    policy_kernel<<<GRIDX, NTHR, SMEM_BYTES>>>(x, Wg, bg, Wp, bp, Wa, ba, out);
}

// round 5
// speedup vs baseline: 1.3261x; 1.0992x over previous
#include <cuda_runtime.h>

// DPLSafePolicy fused skinny GEMM (16384x2048 @ 2048x13) + softmax/ProbLog epilogue.
// R3: R2 + prefetch.global.L2 streaming. Register double-buffer unchanged (1 stage),
// but consuming LDGs now hit L2 (~250cyc) because lanes prefetch 64 cols (~4 stages)
// ahead plus the next chunk's head. No register or smem cost for the deep pipeline.

#define GRIDX 148
#define NTHR 512
#define NWARPS (GRIDX * (NTHR / 32))
#define HDIM 2048
#define NROWS 16384
#define RPC 4
#define NCHUNK (NROWS / RPC)
#define SMEM_FLOATS (HDIM * 16 + 64)
#define SMEM_BYTES (SMEM_FLOATS * 4)

typedef unsigned long long u64;

__device__ __forceinline__ u64 splat2(float x) {
    u64 r; asm("mov.b64 %0, {%1, %1};" : "=l"(r) : "f"(x)); return r;
}
__device__ __forceinline__ u64 fma2(u64 a, u64 b, u64 c) {
    u64 d; asm("fma.rn.f32x2 %0, %1, %2, %3;" : "=l"(d) : "l"(a), "l"(b), "l"(c)); return d;
}
__device__ __forceinline__ void unpack2(u64 a, float& lo, float& hi) {
    asm("mov.b64 {%0, %1}, %2;" : "=f"(lo), "=f"(hi) : "l"(a));
}
__device__ __forceinline__ void pf_l2(const float* p) {
    asm volatile("prefetch.global.L2 [%0];" :: "l"(p));
}

__global__ void __launch_bounds__(NTHR, 1) policy_kernel(
    const float* __restrict__ x,
    const float* __restrict__ Wg, const float* __restrict__ bg,
    const float* __restrict__ Wp, const float* __restrict__ bp,
    const float* __restrict__ Wa, const float* __restrict__ ba,
    float* __restrict__ out)
{
    extern __shared__ float sw[];
    const int tid = threadIdx.x;

    // Pack weights: sw[c*16 + (c>>8)*4 + j], j=0..3 Wg, 4..7 Wp, 8..12 Wa, 13..15 zero
    for (int idx = tid; idx < HDIM * 16; idx += NTHR) {
        int c = idx >> 4, j = idx & 15;
        float v = 0.0f;
        if (j < 4)       v = Wg[c * 4 + j];
        else if (j < 8)  v = Wp[c * 4 + (j - 4)];
        else if (j < 13) v = Wa[c * 5 + (j - 8)];
        sw[(c << 4) + ((c >> 8) << 2) + j] = v;
    }
    __syncthreads();

    const int warp = tid >> 5, lane = tid & 31;
    const int rsub = lane & 3;       // row within chunk (0..3)
    const int g = lane >> 2;         // column group (0..7), 256 cols each
    const float* wbase = sw + g * 4100;   // (g*256)*16 + g*4

    for (int chunk = warp * GRIDX + blockIdx.x; chunk < NCHUNK; chunk += NWARPS) {
        const int r0 = chunk * RPC;
        const float* xb = x + (size_t)(r0 + rsub) * HDIM + (g << 8);
        // prefetch base == xb (lane covers its own (row, group) slice of this chunk)
        const int nchunk2 = chunk + NWARPS;
        const float* xbn = x + (size_t)(nchunk2 * RPC + rsub) * HDIM + (g << 8);
        const bool has_next = (nchunk2 < NCHUNK);

        u64 acc0 = 0, acc1 = 0, acc2 = 0, acc3 = 0, acc4 = 0, acc5 = 0, acc6 = 0;

        // stage buffers: 16 columns
        float4 c0 = *(const float4*)(xb);
        float4 c1 = *(const float4*)(xb + 4);
        float4 c2 = *(const float4*)(xb + 8);
        float4 c3 = *(const float4*)(xb + 12);

#define COLSTEP(xv, off) { \
            const double2* q = (const double2*)(wbase + (off)); \
            double2 q0 = q[0], q1 = q[1], q2 = q[2], q3 = q[3]; \
            u64 xx = splat2(xv); \
            acc0 = fma2(xx, __double_as_longlong(q0.x), acc0); \
            acc1 = fma2(xx, __double_as_longlong(q0.y), acc1); \
            acc2 = fma2(xx, __double_as_longlong(q1.x), acc2); \
            acc3 = fma2(xx, __double_as_longlong(q1.y), acc3); \
            acc4 = fma2(xx, __double_as_longlong(q2.x), acc4); \
            acc5 = fma2(xx, __double_as_longlong(q2.y), acc5); \
            acc6 = fma2(xx, __double_as_longlong(q3.x), acc6); \
        }
#define QUAD(cl, b) { \
            int wo = (cl) << 4; \
            COLSTEP(b.x, wo);      COLSTEP(b.y, wo + 16); \
            COLSTEP(b.z, wo + 32); COLSTEP(b.w, wo + 48); \
        }
#define GRP16(cl) { \
            QUAD((cl), c0); QUAD((cl) + 4, c1); \
            QUAD((cl) + 8, c2); QUAD((cl) + 12, c3); \
        }

#pragma unroll 1
        for (int cl = 0; cl < 240; cl += 16) {
            // L2 prefetch: 64 cols (~4 stages) ahead, one 128B line per lane,
            // every other stage (each prefetch covers 32 cols).
            if ((cl & 31) == 0) {
                int pfc = cl + 64; if (pfc > 224) pfc = 224;
                pf_l2(xb + pfc);
            }
            // next chunk's head (cols 0..63) so its initial loads hit L2 too
            if (cl == 96 && has_next) pf_l2(xbn);
            if (cl == 128 && has_next) pf_l2(xbn + 32);

            // prefetch next 16 columns into registers before consuming stage
            float4 n0 = *(const float4*)(xb + cl + 16);
            float4 n1 = *(const float4*)(xb + cl + 20);
            float4 n2 = *(const float4*)(xb + cl + 24);
            float4 n3 = *(const float4*)(xb + cl + 28);
            GRP16(cl);
            c0 = n0; c1 = n1; c2 = n2; c3 = n3;
        }
        GRP16(240);

        // Unpack 7 packed accumulators -> 13 logit partials (+1 pad: weight==0)
        float v[13]; float pad;
        unpack2(acc0, v[0], v[1]);   unpack2(acc1, v[2], v[3]);
        unpack2(acc2, v[4], v[5]);   unpack2(acc3, v[6], v[7]);
        unpack2(acc4, v[8], v[9]);   unpack2(acc5, v[10], v[11]);
        unpack2(acc6, v[12], pad);

        // Reduce across the 8 column groups (lane bits 2,3,4)
#pragma unroll
        for (int off = 4; off <= 16; off <<= 1) {
#pragma unroll
            for (int j = 0; j < 13; j++)
                v[j] += __shfl_xor_sync(0xffffffffu, v[j], off);
        }

        if (g == 0) {
            const int row = r0 + rsub;
            // ghost softmax
            float l0 = v[0] + bg[0], l1 = v[1] + bg[1], l2 = v[2] + bg[2], l3 = v[3] + bg[3];
            float mg = fmaxf(fmaxf(l0, l1), fmaxf(l2, l3));
            float eg0 = __expf(l0 - mg), eg1 = __expf(l1 - mg), eg2 = __expf(l2 - mg), eg3 = __expf(l3 - mg);
            float sg = eg0 + eg1 + eg2 + eg3;
            // pacman softmax
            float p0 = v[4] + bp[0], p1 = v[5] + bp[1], p2 = v[6] + bp[2], p3 = v[7] + bp[3];
            float mp = fmaxf(fmaxf(p0, p1), fmaxf(p2, p3));
            float ep0 = __expf(p0 - mp), ep1 = __expf(p1 - mp), ep2 = __expf(p2 - mp), ep3 = __expf(p3 - mp);
            float sp = ep0 + ep1 + ep2 + ep3;
            // action softmax numerators
            float q0 = v[8] + ba[0], q1 = v[9] + ba[1], q2 = v[10] + ba[2], q3 = v[11] + ba[3], q4 = v[12] + ba[4];
            float ma = fmaxf(fmaxf(fmaxf(q0, q1), fmaxf(q2, q3)), q4);
            float ea0 = __expf(q0 - ma), ea1 = __expf(q1 - ma), ea2 = __expf(q2 - ma),
                  ea3 = __expf(q3 - ma), ea4 = __expf(q4 - ma);
            // unsafe terms (cells: 0=(0,0),1=(0,1),2=(1,0),3=(1,1))
            float t0 = ep0 * eg0 + ep1 * eg1 + ep2 * eg2 + ep3 * eg3;  // stay
            float t1 = ep0 * eg1 + ep2 * eg3;                           // up
            float t2 = ep1 * eg0 + ep3 * eg2;                           // down
            float inv = 1.0f / (sg * sp);
            float j0 = ea0 * (1.0f - t0 * inv);
            float j1 = ea1 * (1.0f - t1 * inv);
            float j2 = ea2 * (1.0f - t2 * inv);
            float s = j0 + j1 + j2 + ea3 + ea4;
            float is = 1.0f / s;
            float* o = out + (size_t)row * 5;
            o[0] = j0 * is; o[1] = j1 * is; o[2] = j2 * is; o[3] = ea3 * is; o[4] = ea4 * is;
        }
    }
}

extern "C" void kernel_launch(void* const* d_in, const int* in_sizes, int n_in,
                              void* d_out, int out_size)
{
    const float* x  = (const float*)d_in[0];
    const float* Wg = (const float*)d_in[1];
    const float* bg = (const float*)d_in[2];
    const float* Wp = (const float*)d_in[3];
    const float* bp = (const float*)d_in[4];
    const float* Wa = (const float*)d_in[5];
    const float* ba = (const float*)d_in[6];
    float* out = (float*)d_out;

    cudaFuncSetAttribute(policy_kernel, cudaFuncAttributeMaxDynamicSharedMemorySize, SMEM_BYTES);
    policy_kernel<<<GRIDX, NTHR, SMEM_BYTES>>>(x, Wg, bg, Wp, bp, Wa, ba, out);
}

// round 6
// speedup vs baseline: 1.4738x; 1.1113x over previous
#include <cuda_runtime.h>

// DPLSafePolicy fused skinny GEMM (16384x2048 @ 2048x13) + softmax/ProbLog epilogue.
// R4: weights as 13 column-planes (stride 2076, swizzled) -> smem 105KB -> 2 CTAs/SM
// -> 32 warps/SM. Packed-K fma.rn.f32x2: x loaded as double2 (pre-packed pairs),
// one LDS.128 per output per 4 K-cols. Single wave: 4736 warps >= 4096 chunks.

#define GRIDX 296              // 2 CTAs per SM
#define NTHR 512
#define HDIM 2048
#define NROWS 16384
#define RPC 4
#define NCHUNK (NROWS / RPC)   // 4096
#define PS 2076                // plane stride in floats (>= 2047+28+1, 16B aligned)
#define SMEM_FLOATS (13 * PS)
#define SMEM_BYTES (SMEM_FLOATS * 4)

typedef unsigned long long u64;

__device__ __forceinline__ u64 fma2(u64 a, u64 b, u64 c) {
    u64 d; asm("fma.rn.f32x2 %0, %1, %2, %3;" : "=l"(d) : "l"(a), "l"(b), "l"(c)); return d;
}
__device__ __forceinline__ void unpack2(u64 a, float& lo, float& hi) {
    asm("mov.b64 {%0, %1}, %2;" : "=f"(lo), "=f"(hi) : "l"(a));
}
__device__ __forceinline__ void pf_l2(const float* p) {
    asm volatile("prefetch.global.L2 [%0];" :: "l"(p));
}
// swizzled column offset within a plane: c + (c>>8)*4
__device__ __forceinline__ int swz(int c) { return c + ((c >> 8) << 2); }

__global__ void __launch_bounds__(NTHR, 2) policy_kernel(
    const float* __restrict__ x,
    const float* __restrict__ Wg, const float* __restrict__ bg,
    const float* __restrict__ Wp, const float* __restrict__ bp,
    const float* __restrict__ Wa, const float* __restrict__ ba,
    float* __restrict__ out)
{
    extern __shared__ float sw[];
    const int tid = threadIdx.x;

    // ---- Pack weights into 13 planes: sw[j*PS + swz(c)] = W[c, j] ----
    // Wg -> planes 0..3, Wp -> planes 4..7, Wa -> planes 8..12. Coalesced LDG, scattered STS.
    for (int t = tid; t < HDIM * 4; t += NTHR) {
        int c = t >> 2, j = t & 3;
        float vg = Wg[t], vp = Wp[t];
        sw[j * PS + swz(c)] = vg;
        sw[(j + 4) * PS + swz(c)] = vp;
    }
    for (int t = tid; t < HDIM * 5; t += NTHR) {
        int c = t / 5, j = t - c * 5;
        sw[(j + 8) * PS + swz(c)] = Wa[t];
    }
    __syncthreads();

    const int warp = tid >> 5, lane = tid & 31;
    const int chunk = blockIdx.x * (NTHR / 32) + warp;   // global warp id == chunk
    if (chunk >= NCHUNK) return;

    const int rsub = lane & 3;        // row within chunk (0..3)
    const int g = lane >> 2;          // column group (0..7), 256 cols each
    const int r0 = chunk * RPC;
    const float* xb = x + (size_t)(r0 + rsub) * HDIM + (g << 8);
    const float* wb = sw + g * 260;   // swz(g*256) = g*256 + g*4

    // 13 packed accumulators: acc[j] = (sum over even K, sum over odd K)
    u64 acc[13];
#pragma unroll
    for (int j = 0; j < 13; j++) acc[j] = 0;

#pragma unroll 1
    for (int cl = 0; cl < 256; cl += 8) {
        if ((cl & 31) == 0) {                       // L2 prefetch ~2 lines ahead
            int pfc = cl + 64; if (pfc > 224) pfc = 224;
            pf_l2(xb + pfc);
        }
        // x pairs, already packed by LDG.128: (x0,x1),(x2,x3),(x4,x5),(x6,x7)
        double2 xa = *(const double2*)(xb + cl);
        double2 xc = *(const double2*)(xb + cl + 4);
        u64 x01 = __double_as_longlong(xa.x), x23 = __double_as_longlong(xa.y);
        u64 x45 = __double_as_longlong(xc.x), x67 = __double_as_longlong(xc.y);
#pragma unroll
        for (int j = 0; j < 13; j++) {
            const float* wp_ = wb + j * PS + cl;
            double2 w0 = *(const double2*)(wp_);       // (w[cl],w[cl+1]),(w[cl+2],w[cl+3])
            double2 w1 = *(const double2*)(wp_ + 4);
            u64 a = acc[j];
            a = fma2(x01, __double_as_longlong(w0.x), a);
            a = fma2(x23, __double_as_longlong(w0.y), a);
            a = fma2(x45, __double_as_longlong(w1.x), a);
            a = fma2(x67, __double_as_longlong(w1.y), a);
            acc[j] = a;
        }
    }

    // horizontal: even+odd partials
    float v[13];
#pragma unroll
    for (int j = 0; j < 13; j++) {
        float lo, hi; unpack2(acc[j], lo, hi); v[j] = lo + hi;
    }

    // Reduce across the 8 column groups (lane bits 2,3,4)
#pragma unroll
    for (int off = 4; off <= 16; off <<= 1) {
#pragma unroll
        for (int j = 0; j < 13; j++)
            v[j] += __shfl_xor_sync(0xffffffffu, v[j], off);
    }

    if (g == 0) {
        const int row = r0 + rsub;
        // ghost softmax
        float l0 = v[0] + bg[0], l1 = v[1] + bg[1], l2 = v[2] + bg[2], l3 = v[3] + bg[3];
        float mg = fmaxf(fmaxf(l0, l1), fmaxf(l2, l3));
        float eg0 = __expf(l0 - mg), eg1 = __expf(l1 - mg), eg2 = __expf(l2 - mg), eg3 = __expf(l3 - mg);
        float sg = eg0 + eg1 + eg2 + eg3;
        // pacman softmax
        float p0 = v[4] + bp[0], p1 = v[5] + bp[1], p2 = v[6] + bp[2], p3 = v[7] + bp[3];
        float mp = fmaxf(fmaxf(p0, p1), fmaxf(p2, p3));
        float ep0 = __expf(p0 - mp), ep1 = __expf(p1 - mp), ep2 = __expf(p2 - mp), ep3 = __expf(p3 - mp);
        float sp = ep0 + ep1 + ep2 + ep3;
        // action softmax numerators
        float q0 = v[8] + ba[0], q1 = v[9] + ba[1], q2 = v[10] + ba[2], q3 = v[11] + ba[3], q4 = v[12] + ba[4];
        float ma = fmaxf(fmaxf(fmaxf(q0, q1), fmaxf(q2, q3)), q4);
        float ea0 = __expf(q0 - ma), ea1 = __expf(q1 - ma), ea2 = __expf(q2 - ma),
              ea3 = __expf(q3 - ma), ea4 = __expf(q4 - ma);
        // unsafe terms (cells: 0=(0,0),1=(0,1),2=(1,0),3=(1,1))
        float t0 = ep0 * eg0 + ep1 * eg1 + ep2 * eg2 + ep3 * eg3;  // stay
        float t1 = ep0 * eg1 + ep2 * eg3;                           // up
        float t2 = ep1 * eg0 + ep3 * eg2;                           // down
        float inv = 1.0f / (sg * sp);
        float j0 = ea0 * (1.0f - t0 * inv);
        float j1 = ea1 * (1.0f - t1 * inv);
        float j2 = ea2 * (1.0f - t2 * inv);
        float s = j0 + j1 + j2 + ea3 + ea4;
        float is = 1.0f / s;
        float* o = out + (size_t)row * 5;
        o[0] = j0 * is; o[1] = j1 * is; o[2] = j2 * is; o[3] = ea3 * is; o[4] = ea4 * is;
    }
}

extern "C" void kernel_launch(void* const* d_in, const int* in_sizes, int n_in,
                              void* d_out, int out_size)
{
    const float* x  = (const float*)d_in[0];
    const float* Wg = (const float*)d_in[1];
    const float* bg = (const float*)d_in[2];
    const float* Wp = (const float*)d_in[3];
    const float* bp = (const float*)d_in[4];
    const float* Wa = (const float*)d_in[5];
    const float* ba = (const float*)d_in[6];
    float* out = (float*)d_out;

    cudaFuncSetAttribute(policy_kernel, cudaFuncAttributeMaxDynamicSharedMemorySize, SMEM_BYTES);
    policy_kernel<<<GRIDX, NTHR, SMEM_BYTES>>>(x, Wg, bg, Wp, bp, Wa, ba, out);
}

// round 8
// speedup vs baseline: 1.6192x; 1.0987x over previous
#include <cuda_runtime.h>

// DPLSafePolicy fused skinny GEMM (16384x2048 @ 2048x13) + softmax/ProbLog epilogue.
// R5: R4 (13-plane smem weights, 2 CTAs/SM, packed-K fma.f32x2) + restored explicit
// x register double-buffer (next 8 cols in flight during compute) + warp-interleaved
// chunk mapping so idle warp slots spread evenly across SMs. L2 prefetch 64 ahead.

#define GRIDX 296              // 2 CTAs per SM
#define NTHR 512
#define NWARPS (GRIDX * (NTHR / 32))   // 4736
#define HDIM 2048
#define NROWS 16384
#define RPC 4
#define NCHUNK (NROWS / RPC)   // 4096
#define PS 2076                // plane stride in floats
#define SMEM_FLOATS (13 * PS)
#define SMEM_BYTES (SMEM_FLOATS * 4)

typedef unsigned long long u64;

__device__ __forceinline__ u64 fma2(u64 a, u64 b, u64 c) {
    u64 d; asm("fma.rn.f32x2 %0, %1, %2, %3;" : "=l"(d) : "l"(a), "l"(b), "l"(c)); return d;
}
__device__ __forceinline__ void unpack2(u64 a, float& lo, float& hi) {
    asm("mov.b64 {%0, %1}, %2;" : "=f"(lo), "=f"(hi) : "l"(a));
}
__device__ __forceinline__ void pf_l2(const float* p) {
    asm volatile("prefetch.global.L2 [%0];" :: "l"(p));
}
__device__ __forceinline__ int swz(int c) { return c + ((c >> 8) << 2); }

__global__ void __launch_bounds__(NTHR, 2) policy_kernel(
    const float* __restrict__ x,
    const float* __restrict__ Wg, const float* __restrict__ bg,
    const float* __restrict__ Wp, const float* __restrict__ bp,
    const float* __restrict__ Wa, const float* __restrict__ ba,
    float* __restrict__ out)
{
    extern __shared__ float sw[];
    const int tid = threadIdx.x;

    // Pack weights into 13 planes: sw[j*PS + swz(c)] = W[c, j]
    for (int t = tid; t < HDIM * 4; t += NTHR) {
        int c = t >> 2, j = t & 3;
        float vg = Wg[t], vp = Wp[t];
        sw[j * PS + swz(c)] = vg;
        sw[(j + 4) * PS + swz(c)] = vp;
    }
    for (int t = tid; t < HDIM * 5; t += NTHR) {
        int c = t / 5, j = t - c * 5;
        sw[(j + 8) * PS + swz(c)] = Wa[t];
    }
    __syncthreads();

    const int warp = tid >> 5, lane = tid & 31;
    // interleaved so idle slots (chunk >= NCHUNK) spread evenly across SMs
    const int chunk = warp * GRIDX + blockIdx.x;
    if (chunk >= NCHUNK) return;

    const int rsub = lane & 3;        // row within chunk (0..3)
    const int g = lane >> 2;          // column group (0..7), 256 cols each
    const int r0 = chunk * RPC;
    const float* xb = x + (size_t)(r0 + rsub) * HDIM + (g << 8);
    const float* wb = sw + g * 260;   // swz(g*256)

    u64 acc[13];
#pragma unroll
    for (int j = 0; j < 13; j++) acc[j] = 0;

    // current-stage x pairs (8 cols = 4 packed pairs)
    double2 xa = *(const double2*)(xb);
    double2 xc = *(const double2*)(xb + 4);
    u64 x01 = __double_as_longlong(xa.x), x23 = __double_as_longlong(xa.y);
    u64 x45 = __double_as_longlong(xc.x), x67 = __double_as_longlong(xc.y);

#pragma unroll 1
    for (int cl = 0; cl < 256; cl += 8) {
        // issue next-stage LDGs first (1-stage double buffer)
        u64 n01 = 0, n23 = 0, n45 = 0, n67 = 0;
        if (cl < 248) {
            double2 na = *(const double2*)(xb + cl + 8);
            double2 nc = *(const double2*)(xb + cl + 12);
            n01 = __double_as_longlong(na.x); n23 = __double_as_longlong(na.y);
            n45 = __double_as_longlong(nc.x); n67 = __double_as_longlong(nc.y);
        }
        if ((cl & 31) == 0) {                  // L2 prefetch ~2 lines ahead
            int pfc = cl + 64; if (pfc > 224) pfc = 224;
            pf_l2(xb + pfc);
        }
#pragma unroll
        for (int j = 0; j < 13; j++) {
            const float* wp_ = wb + j * PS + cl;
            double2 w0 = *(const double2*)(wp_);
            double2 w1 = *(const double2*)(wp_ + 4);
            u64 a = acc[j];
            a = fma2(x01, __double_as_longlong(w0.x), a);
            a = fma2(x23, __double_as_longlong(w0.y), a);
            a = fma2(x45, __double_as_longlong(w1.x), a);
            a = fma2(x67, __double_as_longlong(w1.y), a);
            acc[j] = a;
        }
        x01 = n01; x23 = n23; x45 = n45; x67 = n67;
    }

    float v[13];
#pragma unroll
    for (int j = 0; j < 13; j++) {
        float lo, hi; unpack2(acc[j], lo, hi); v[j] = lo + hi;
    }

    // Reduce across the 8 column groups (lane bits 2,3,4)
#pragma unroll
    for (int off = 4; off <= 16; off <<= 1) {
#pragma unroll
        for (int j = 0; j < 13; j++)
            v[j] += __shfl_xor_sync(0xffffffffu, v[j], off);
    }

    if (g == 0) {
        const int row = r0 + rsub;
        float l0 = v[0] + bg[0], l1 = v[1] + bg[1], l2 = v[2] + bg[2], l3 = v[3] + bg[3];
        float mg = fmaxf(fmaxf(l0, l1), fmaxf(l2, l3));
        float eg0 = __expf(l0 - mg), eg1 = __expf(l1 - mg), eg2 = __expf(l2 - mg), eg3 = __expf(l3 - mg);
        float sg = eg0 + eg1 + eg2 + eg3;
        float p0 = v[4] + bp[0], p1 = v[5] + bp[1], p2 = v[6] + bp[2], p3 = v[7] + bp[3];
        float mp = fmaxf(fmaxf(p0, p1), fmaxf(p2, p3));
        float ep0 = __expf(p0 - mp), ep1 = __expf(p1 - mp), ep2 = __expf(p2 - mp), ep3 = __expf(p3 - mp);
        float sp = ep0 + ep1 + ep2 + ep3;
        float q0 = v[8] + ba[0], q1 = v[9] + ba[1], q2 = v[10] + ba[2], q3 = v[11] + ba[3], q4 = v[12] + ba[4];
        float ma = fmaxf(fmaxf(fmaxf(q0, q1), fmaxf(q2, q3)), q4);
        float ea0 = __expf(q0 - ma), ea1 = __expf(q1 - ma), ea2 = __expf(q2 - ma),
              ea3 = __expf(q3 - ma), ea4 = __expf(q4 - ma);
        float t0 = ep0 * eg0 + ep1 * eg1 + ep2 * eg2 + ep3 * eg3;  // stay
        float t1 = ep0 * eg1 + ep2 * eg3;                           // up
        float t2 = ep1 * eg0 + ep3 * eg2;                           // down
        float inv = 1.0f / (sg * sp);
        float j0 = ea0 * (1.0f - t0 * inv);
        float j1 = ea1 * (1.0f - t1 * inv);
        float j2 = ea2 * (1.0f - t2 * inv);
        float s = j0 + j1 + j2 + ea3 + ea4;
        float is = 1.0f / s;
        float* o = out + (size_t)row * 5;
        o[0] = j0 * is; o[1] = j1 * is; o[2] = j2 * is; o[3] = ea3 * is; o[4] = ea4 * is;
    }
}

extern "C" void kernel_launch(void* const* d_in, const int* in_sizes, int n_in,
                              void* d_out, int out_size)
{
    const float* x  = (const float*)d_in[0];
    const float* Wg = (const float*)d_in[1];
    const float* bg = (const float*)d_in[2];
    const float* Wp = (const float*)d_in[3];
    const float* bp = (const float*)d_in[4];
    const float* Wa = (const float*)d_in[5];
    const float* ba = (const float*)d_in[6];
    float* out = (float*)d_out;

    cudaFuncSetAttribute(policy_kernel, cudaFuncAttributeMaxDynamicSharedMemorySize, SMEM_BYTES);
    policy_kernel<<<GRIDX, NTHR, SMEM_BYTES>>>(x, Wg, bg, Wp, bp, Wa, ba, out);
}